// round 1
// baseline (speedup 1.0000x reference)
#include <cuda_runtime.h>

// Shapes fixed by the problem: bz=4, C=32, H=W=256, NF=12 focal slices.
#define NF   12
#define BZ   4
#define C_   32
#define HW   65536            // 256*256 (power of two)
#define CHW  (C_ * HW)        // 2,097,152
#define CHW4 (CHW / 4)        // 524,288 = 2^19
#define HW4  (HW / 4)         // 16,384

#define BPB  128              // reduction blocks per (b,f) pair
#define TPB  256

// Scratch (no allocation allowed): deterministic per-block partial sums + selection.
__device__ float g_part[BZ * NF * BPB];
__device__ int   g_sel[2 * BZ];   // [0..BZ) = i per batch, [BZ..2BZ) = j per batch

// ---------------------------------------------------------------------------
// Kernel 1: per-(b,f) partial sums of |sal * (x - x_focal)|.
// grid = (BPB, BZ*NF). Each block owns a contiguous 16384-element chunk.
// ---------------------------------------------------------------------------
__global__ __launch_bounds__(TPB) void k_reduce(const float* __restrict__ x,
                                                const float* __restrict__ xf,
                                                const float* __restrict__ sal) {
    const int bf = blockIdx.y;
    const int b  = bf / NF;
    const int f  = bf % NF;

    const float4* __restrict__ xp = (const float4*)(x   + (size_t)b * CHW);
    const float4* __restrict__ fp = (const float4*)(xf  + ((size_t)f * BZ + b) * CHW);
    const float4* __restrict__ sp = (const float4*)(sal + (size_t)b * HW);

    const int chunk = CHW4 / BPB;            // 4096 float4 per block
    const int base  = blockIdx.x * chunk;

    float acc = 0.f;
#pragma unroll 4
    for (int i = threadIdx.x; i < chunk; i += TPB) {
        const int v = base + i;              // float4 index within [0, CHW4)
        float4 a = xp[v];
        float4 g = fp[v];
        float4 s = sp[v & (HW4 - 1)];        // sal broadcast over channels
        acc += fabsf(s.x * (a.x - g.x));
        acc += fabsf(s.y * (a.y - g.y));
        acc += fabsf(s.z * (a.z - g.z));
        acc += fabsf(s.w * (a.w - g.w));
    }

    __shared__ float sh[TPB];
    sh[threadIdx.x] = acc;
    __syncthreads();
#pragma unroll
    for (int s = TPB / 2; s > 32; s >>= 1) {
        if (threadIdx.x < s) sh[threadIdx.x] += sh[threadIdx.x + s];
        __syncthreads();
    }
    if (threadIdx.x < 32) {
        float v = sh[threadIdx.x] + sh[threadIdx.x + 32];
#pragma unroll
        for (int o = 16; o > 0; o >>= 1)
            v += __shfl_down_sync(0xffffffffu, v, o);
        if (threadIdx.x == 0)
            g_part[bf * BPB + blockIdx.x] = v;
    }
}

// ---------------------------------------------------------------------------
// Kernel 2: single block. Deterministic double-precision final reduction of
// the 48 MAE sums, then per-batch row-major first-max over i<j pairs of
// (mae_i - mae_j)^2 with strict '>' (matches jnp.argmax first-occurrence and
// torch's keep-(0,0)-unless-strictly-positive behavior).
// ---------------------------------------------------------------------------
__global__ void k_select() {
    __shared__ double mae[BZ * NF];
    const int t = threadIdx.x;
    if (t < BZ * NF) {
        double s = 0.0;
#pragma unroll 8
        for (int i = 0; i < BPB; ++i) s += (double)g_part[t * BPB + i];
        mae[t] = s;   // scale by 1/CHW irrelevant for argmax / >0 test
    }
    __syncthreads();
    if (t < BZ) {
        const int b = t;
        double best = -1.0;
        int bi = 0, bj = 0;
        for (int i = 0; i < NF; ++i) {
            for (int j = i + 1; j < NF; ++j) {
                double d = mae[b * NF + i] - mae[b * NF + j];
                double v = d * d;            // 0.5 factor irrelevant for sign/order
                if (v > best) { best = v; bi = i; bj = j; }
            }
        }
        if (!(best > 0.0)) { bi = 0; bj = 0; }
        g_sel[b]      = bi;
        g_sel[BZ + b] = bj;
    }
}

// ---------------------------------------------------------------------------
// Kernel 3: gather-copy out[which, b] = x_focal[sel*BZ + b], float4 vectorized.
// Output rows r in [0, 2*BZ): b = r % BZ, which = r / BZ.
// ---------------------------------------------------------------------------
__global__ __launch_bounds__(TPB) void k_copy(const float* __restrict__ xf,
                                              float* __restrict__ out) {
    const long long q = (long long)blockIdx.x * TPB + threadIdx.x; // float4 idx
    // total = 2*BZ*CHW4 = 4,194,304; grid sized exactly
    const int r  = (int)(q >> 19);          // q / CHW4
    const int n4 = (int)(q & (CHW4 - 1));
    const int b     = r & (BZ - 1);
    const int which = r >> 2;               // r / BZ  (BZ == 4)
    const int f = g_sel[which * BZ + b];
    const float4* __restrict__ src = (const float4*)(xf + ((size_t)f * BZ + b) * CHW);
    ((float4*)out)[q] = src[n4];
}

// ---------------------------------------------------------------------------
extern "C" void kernel_launch(void* const* d_in, const int* in_sizes, int n_in,
                              void* d_out, int out_size) {
    const float* x    = (const float*)d_in[0];   // [4,32,256,256]
    const float* xf   = (const float*)d_in[1];   // [48,32,256,256]
    const float* sal  = (const float*)d_in[2];   // [4,1,256,256]
    float*       out  = (float*)d_out;           // [8,32,256,256]

    dim3 gridR(BPB, BZ * NF);
    k_reduce<<<gridR, TPB>>>(x, xf, sal);
    k_select<<<1, 64>>>();
    const long long total4 = 2LL * BZ * CHW4;    // 4,194,304
    k_copy<<<(unsigned)(total4 / TPB), TPB>>>(xf, out);
}

// round 2
// speedup vs baseline: 1.1544x; 1.1544x over previous
#include <cuda_runtime.h>

// Shapes fixed by the problem: bz=4, C=32, H=W=256, NF=12 focal slices.
#define NF   12
#define BZ   4
#define C_   32
#define HW   65536            // 256*256
#define CHW  (C_ * HW)        // 2,097,152
#define CHW4 (CHW / 4)        // 524,288 = 2^19
#define HW4  (HW / 4)         // 16,384

#define BPB  128              // reduction blocks per (b, chunk-slice)
#define TPB  256
#define CHUNK (CHW4 / BPB)    // 4096 float4 per block

// Scratch (no allocation allowed).
__device__ float g_part[BZ * NF * BPB];
__device__ int   g_sel[2 * BZ];   // [0..BZ) = i per batch, [BZ..2BZ) = j per batch

// ---------------------------------------------------------------------------
// Kernel 1: each block owns one (b, chunk) and accumulates ALL 12 focal MAEs.
// 14 independent 16B loads in flight per iteration -> high MLP, DRAM-bound.
// grid = (BPB, BZ).
// ---------------------------------------------------------------------------
__global__ __launch_bounds__(TPB, 2) void k_reduce(const float* __restrict__ x,
                                                   const float* __restrict__ xf,
                                                   const float* __restrict__ sal) {
    const int b    = blockIdx.y;
    const int base = blockIdx.x * CHUNK;

    const float4* __restrict__ xp = (const float4*)(x   + (size_t)b * CHW);
    const float4* __restrict__ sp = (const float4*)(sal + (size_t)b * HW);

    const float4* __restrict__ fp[NF];
#pragma unroll
    for (int f = 0; f < NF; ++f)
        fp[f] = (const float4*)(xf + ((size_t)f * BZ + b) * CHW);

    float acc[NF];
#pragma unroll
    for (int f = 0; f < NF; ++f) acc[f] = 0.f;

    for (int i = threadIdx.x; i < CHUNK; i += TPB) {
        const int v = base + i;
        const float4 a = xp[v];
        const float4 s = sp[v & (HW4 - 1)];       // sal broadcast over channels
        // 12 independent streaming loads (no reuse of xf in L2)
        float4 g[NF];
#pragma unroll
        for (int f = 0; f < NF; ++f) g[f] = __ldcs(&fp[f][v]);
#pragma unroll
        for (int f = 0; f < NF; ++f) {
            acc[f] += fabsf(s.x * (a.x - g[f].x));
            acc[f] += fabsf(s.y * (a.y - g[f].y));
            acc[f] += fabsf(s.z * (a.z - g[f].z));
            acc[f] += fabsf(s.w * (a.w - g[f].w));
        }
    }

    // Warp shuffle reduce each of the 12 accumulators, then combine warps.
    const int lane = threadIdx.x & 31;
    const int warp = threadIdx.x >> 5;
#pragma unroll
    for (int f = 0; f < NF; ++f) {
        float v = acc[f];
#pragma unroll
        for (int o = 16; o > 0; o >>= 1)
            v += __shfl_down_sync(0xffffffffu, v, o);
        acc[f] = v;   // valid on lane 0
    }

    __shared__ float sh[TPB / 32][NF];
    if (lane == 0) {
#pragma unroll
        for (int f = 0; f < NF; ++f) sh[warp][f] = acc[f];
    }
    __syncthreads();
    if (threadIdx.x < NF) {
        const int f = threadIdx.x;
        float s = 0.f;
#pragma unroll
        for (int w = 0; w < TPB / 32; ++w) s += sh[w][f];
        g_part[(b * NF + f) * BPB + blockIdx.x] = s;
    }
}

// ---------------------------------------------------------------------------
// Kernel 2: final reduction (double, fixed order) + pair selection.
// 4 threads per (b,f): each sums 32 partials, combined in fixed order.
// ---------------------------------------------------------------------------
__global__ void k_select() {
    __shared__ double part4[BZ * NF][4];
    __shared__ double mae[BZ * NF];
    const int t = threadIdx.x;

    if (t < BZ * NF * 4) {
        const int bf = t >> 2;
        const int g  = t & 3;
        double s = 0.0;
#pragma unroll 8
        for (int k = 0; k < BPB / 4; ++k)
            s += (double)g_part[bf * BPB + g * (BPB / 4) + k];
        part4[bf][g] = s;
    }
    __syncthreads();
    if (t < BZ * NF)
        mae[t] = ((part4[t][0] + part4[t][1]) + part4[t][2]) + part4[t][3];
    __syncthreads();

    if (t < BZ) {
        const int b = t;
        double best = -1.0;
        int bi = 0, bj = 0;
        for (int i = 0; i < NF; ++i)
            for (int j = i + 1; j < NF; ++j) {
                const double d = mae[b * NF + i] - mae[b * NF + j];
                const double v = d * d;     // 0.5 factor irrelevant for ordering
                if (v > best) { best = v; bi = i; bj = j; }
            }
        if (!(best > 0.0)) { bi = 0; bj = 0; }
        g_sel[b]      = bi;
        g_sel[BZ + b] = bj;
    }
}

// ---------------------------------------------------------------------------
// Kernel 3: gather-copy, 4 float4 per thread for MLP, streaming access.
// Block chunk = TPB*4 = 1024 float4, which divides CHW4 -> one slice per block.
// ---------------------------------------------------------------------------
#define CPT 4
__global__ __launch_bounds__(TPB) void k_copy(const float* __restrict__ xf,
                                              float* __restrict__ out) {
    const long long q0 = (long long)blockIdx.x * (TPB * CPT);
    const int r     = (int)(q0 >> 19);      // output row 0..7 (constant per block)
    const int b     = r & (BZ - 1);
    const int which = r >> 2;
    const int f     = g_sel[which * BZ + b];

    const float4* __restrict__ src = (const float4*)(xf + ((size_t)f * BZ + b) * CHW);
    float4* __restrict__ dst = (float4*)out;

#pragma unroll
    for (int c = 0; c < CPT; ++c) {
        const long long q = q0 + c * TPB + threadIdx.x;
        const int n4 = (int)(q & (CHW4 - 1));
        __stcs(&dst[q], __ldcs(&src[n4]));
    }
}

// ---------------------------------------------------------------------------
extern "C" void kernel_launch(void* const* d_in, const int* in_sizes, int n_in,
                              void* d_out, int out_size) {
    const float* x   = (const float*)d_in[0];   // [4,32,256,256]
    const float* xf  = (const float*)d_in[1];   // [48,32,256,256]
    const float* sal = (const float*)d_in[2];   // [4,1,256,256]
    float*       out = (float*)d_out;           // [8,32,256,256]

    dim3 gridR(BPB, BZ);
    k_reduce<<<gridR, TPB>>>(x, xf, sal);
    k_select<<<1, 192>>>();
    const unsigned blocksC = (unsigned)((2LL * BZ * CHW4) / (TPB * CPT)); // 4096
    k_copy<<<blocksC, TPB>>>(xf, out);
}